// round 1
// baseline (speedup 1.0000x reference)
#include <cuda_runtime.h>
#include <math_constants.h>

#define BATCH   32
#define LCACHE  8192
#define NKV     4
#define NH      16
#define HD      128
#define HID     2048
#define QKVW    3072          // 2048 q + 512 k + 512 v
#define GROUPS  4             // NH / NKV
#define NSPLIT  16
#define SPLIT_LEN 512         // LCACHE / NSPLIT
#define KSPLIT  16

// scale * log2(e) : (1/sqrt(128)) * 1.4426950408889634
#define SCLOG2E (1.4426950408889634f * 0.08838834764831845f)

// ---------------- scratch (device globals; no allocation allowed) ----------
__device__ float g_qkv_part[KSPLIT][BATCH][QKVW];      // 6.3 MB
__device__ float g_qn[BATCH][NH][HD];
__device__ float g_kn[BATCH][NKV][HD];
__device__ float g_vn[BATCH][NKV][HD];
__device__ float g_pacc[BATCH * NKV][NSPLIT][GROUPS][HD];  // 4.2 MB
__device__ float g_pm[BATCH * NKV][NSPLIT][GROUPS];
__device__ float g_pl[BATCH * NKV][NSPLIT][GROUPS];
__device__ float g_attn[BATCH][HID];
__device__ float g_opart[KSPLIT][BATCH][HID];          // 4.2 MB

// ---------------- 1) QKV GEMM: qkv_part[ks] = hidden_tile @ w_tile --------
__global__ void qkv_gemm_k(const float* __restrict__ hidden,
                           const float* __restrict__ w) {
    const int nblk = blockIdx.x;   // 0..23 (128 cols each)
    const int ks   = blockIdx.y;   // 0..15 (128 k each)
    const int tid  = threadIdx.x;  // 128

    __shared__ float hs[BATCH][128];
    for (int i = tid; i < BATCH * 128; i += 128) {
        int b = i >> 7, kk = i & 127;
        hs[b][kk] = hidden[b * HID + ks * 128 + kk];
    }
    __syncthreads();

    const int n = nblk * 128 + tid;
    float acc[BATCH];
#pragma unroll
    for (int b = 0; b < BATCH; b++) acc[b] = 0.f;

    const float* wp = w + (size_t)(ks * 128) * QKVW + n;
#pragma unroll 4
    for (int kk = 0; kk < 128; kk++) {
        float wv = wp[(size_t)kk * QKVW];
#pragma unroll
        for (int b = 0; b < BATCH; b++) acc[b] += hs[b][kk] * wv;
    }
#pragma unroll
    for (int b = 0; b < BATCH; b++) g_qkv_part[ks][b][n] = acc[b];
}

// ---------------- 2) sum partials + bias + per-head RMSNorm ---------------
__global__ void rmsnorm_k(const float* __restrict__ b_qkv,
                          const float* __restrict__ q_gamma,
                          const float* __restrict__ k_gamma) {
    const int seg = blockIdx.x;   // 0..23 : 16 q heads, 4 k heads, 4 v heads
    const int b   = blockIdx.y;   // 0..31
    const int tid = threadIdx.x;  // 128 (= head_dim)
    const int col = seg * 128 + tid;

    float v = b_qkv[col];
#pragma unroll
    for (int s = 0; s < KSPLIT; s++) v += g_qkv_part[s][b][col];

    if (seg < 20) {
        float ss = v * v;
#pragma unroll
        for (int o = 16; o; o >>= 1) ss += __shfl_xor_sync(0xffffffffu, ss, o);
        __shared__ float wsum[4];
        if ((tid & 31) == 0) wsum[tid >> 5] = ss;
        __syncthreads();
        float tot = wsum[0] + wsum[1] + wsum[2] + wsum[3];
        float r = rsqrtf(tot * (1.f / 128.f) + 1e-6f);
        if (seg < 16) g_qn[b][seg][tid]      = v * r * q_gamma[tid];
        else          g_kn[b][seg - 16][tid] = v * r * k_gamma[tid];
    } else {
        g_vn[b][seg - 20][tid] = v;   // V: no norm
    }
}

// ---------------- 3) flash-decode split-K over the caches -----------------
__global__ void __launch_bounds__(256)
attn_k(const float* __restrict__ k_cache, const float* __restrict__ v_cache) {
    const int split = blockIdx.x;           // 0..15
    const int pair  = blockIdx.y;           // 0..127
    const int b     = pair >> 2;
    const int kv    = pair & 3;
    const int tid   = threadIdx.x;
    const int warp  = tid >> 5;
    const int lane  = tid & 31;

    __shared__ float qs[GROUPS][HD];
    __shared__ float s_acc[8][GROUPS][HD];
    __shared__ float s_m[8][GROUPS], s_l[8][GROUPS], s_f[8][GROUPS];
    __shared__ float s_gm[GROUPS], s_gl[GROUPS];

    for (int i = tid; i < GROUPS * HD; i += 256)
        qs[i >> 7][i & 127] = g_qn[b][kv * GROUPS + (i >> 7)][i & 127];
    __syncthreads();

    float qf[GROUPS][4];
#pragma unroll
    for (int h = 0; h < GROUPS; h++) {
        float4 q4 = *(const float4*)&qs[h][lane * 4];
        qf[h][0] = q4.x; qf[h][1] = q4.y; qf[h][2] = q4.z; qf[h][3] = q4.w;
    }

    float m[GROUPS], l[GROUPS], acc[GROUPS][4];
#pragma unroll
    for (int h = 0; h < GROUPS; h++) {
        m[h] = -CUDART_INF_F; l[h] = 0.f;
        acc[h][0] = acc[h][1] = acc[h][2] = acc[h][3] = 0.f;
    }

    const int end = (split == NSPLIT - 1) ? (LCACHE + 1) : (split + 1) * SPLIT_LEN;
    int pos = split * SPLIT_LEN + warp;

    const float* kbase = k_cache + ((size_t)b * LCACHE * NKV + kv) * HD;
    const float* vbase = v_cache + ((size_t)b * LCACHE * NKV + kv) * HD;

    float4 k4, v4;
    if (pos < end) {
        const float4* kp = (pos < LCACHE)
            ? (const float4*)(kbase + (size_t)pos * NKV * HD)
            : (const float4*)&g_kn[b][kv][0];
        const float4* vp = (pos < LCACHE)
            ? (const float4*)(vbase + (size_t)pos * NKV * HD)
            : (const float4*)&g_vn[b][kv][0];
        k4 = kp[lane]; v4 = vp[lane];
    }

    for (; pos < end; pos += 8) {
        // prefetch next iteration (MLP)
        float4 nk4, nv4;
        const int np = pos + 8;
        if (np < end) {
            const float4* kp = (np < LCACHE)
                ? (const float4*)(kbase + (size_t)np * NKV * HD)
                : (const float4*)&g_kn[b][kv][0];
            const float4* vp = (np < LCACHE)
                ? (const float4*)(vbase + (size_t)np * NKV * HD)
                : (const float4*)&g_vn[b][kv][0];
            nk4 = kp[lane]; nv4 = vp[lane];
        }

        float s[GROUPS];
#pragma unroll
        for (int h = 0; h < GROUPS; h++)
            s[h] = qf[h][0] * k4.x + qf[h][1] * k4.y +
                   qf[h][2] * k4.z + qf[h][3] * k4.w;
#pragma unroll
        for (int o = 16; o; o >>= 1) {
#pragma unroll
            for (int h = 0; h < GROUPS; h++)
                s[h] += __shfl_xor_sync(0xffffffffu, s[h], o);
        }

#pragma unroll
        for (int h = 0; h < GROUPS; h++) {
            float sv = s[h] * SCLOG2E;
            if (sv > m[h]) {
                float alpha = exp2f(m[h] - sv);   // 0 on first hit (m = -inf)
                m[h] = sv;
                l[h] = l[h] * alpha + 1.f;
                acc[h][0] = acc[h][0] * alpha + v4.x;
                acc[h][1] = acc[h][1] * alpha + v4.y;
                acc[h][2] = acc[h][2] * alpha + v4.z;
                acc[h][3] = acc[h][3] * alpha + v4.w;
            } else {
                float p = exp2f(sv - m[h]);
                l[h] += p;
                acc[h][0] += p * v4.x;
                acc[h][1] += p * v4.y;
                acc[h][2] += p * v4.z;
                acc[h][3] += p * v4.w;
            }
        }
        k4 = nk4; v4 = nv4;
    }

    // per-warp partials -> smem
#pragma unroll
    for (int h = 0; h < GROUPS; h++) {
        s_m[warp][h] = m[h];
        s_l[warp][h] = l[h];
        s_acc[warp][h][lane * 4 + 0] = acc[h][0];
        s_acc[warp][h][lane * 4 + 1] = acc[h][1];
        s_acc[warp][h][lane * 4 + 2] = acc[h][2];
        s_acc[warp][h][lane * 4 + 3] = acc[h][3];
    }
    __syncthreads();

    if (tid < GROUPS) {
        const int h = tid;
        float gm = -CUDART_INF_F;
#pragma unroll
        for (int w = 0; w < 8; w++) gm = fmaxf(gm, s_m[w][h]);
        float gl = 0.f;
#pragma unroll
        for (int w = 0; w < 8; w++) {
            float f = exp2f(s_m[w][h] - gm);
            s_f[w][h] = f;
            gl += s_l[w][h] * f;
        }
        s_gm[h] = gm; s_gl[h] = gl;
    }
    __syncthreads();

    for (int i = tid; i < GROUPS * HD; i += 256) {
        const int h = i >> 7, d = i & 127;
        float num = 0.f;
#pragma unroll
        for (int w = 0; w < 8; w++) num += s_acc[w][h][d] * s_f[w][h];
        g_pacc[pair][split][h][d] = num;
        if (d == 0) { g_pm[pair][split][h] = s_gm[h]; g_pl[pair][split][h] = s_gl[h]; }
    }
}

// ---------------- 4) combine split partials -> attn_out -------------------
__global__ void combine_k() {
    const int idx  = blockIdx.x;     // 0..511
    const int pair = idx >> 2;
    const int g    = idx & 3;
    const int tid  = threadIdx.x;    // 128

    __shared__ float fs[NSPLIT];
    __shared__ float s_gl;
    if (tid == 0) {
        float gm = -CUDART_INF_F;
#pragma unroll
        for (int s = 0; s < NSPLIT; s++) gm = fmaxf(gm, g_pm[pair][s][g]);
        float gl = 0.f;
#pragma unroll
        for (int s = 0; s < NSPLIT; s++) {
            float f = exp2f(g_pm[pair][s][g] - gm);
            fs[s] = f;
            gl += g_pl[pair][s][g] * f;
        }
        s_gl = gl;
    }
    __syncthreads();

    float num = 0.f;
#pragma unroll
    for (int s = 0; s < NSPLIT; s++) num += g_pacc[pair][s][g][tid] * fs[s];

    const int b = pair >> 2, kv = pair & 3;
    g_attn[b][(kv * GROUPS + g) * HD + tid] = num / s_gl;
}

// ---------------- 5) O projection (k-split partials) ----------------------
__global__ void o_gemm_k(const float* __restrict__ w) {
    const int nblk = blockIdx.x;   // 0..15
    const int ks   = blockIdx.y;   // 0..15
    const int tid  = threadIdx.x;  // 128

    __shared__ float as_[BATCH][128];
    for (int i = tid; i < BATCH * 128; i += 128) {
        int b = i >> 7, kk = i & 127;
        as_[b][kk] = g_attn[b][ks * 128 + kk];
    }
    __syncthreads();

    const int n = nblk * 128 + tid;
    float acc[BATCH];
#pragma unroll
    for (int b = 0; b < BATCH; b++) acc[b] = 0.f;

    const float* wp = w + (size_t)(ks * 128) * HID + n;
#pragma unroll 4
    for (int kk = 0; kk < 128; kk++) {
        float wv = wp[(size_t)kk * HID];
#pragma unroll
        for (int b = 0; b < BATCH; b++) acc[b] += as_[b][kk] * wv;
    }
#pragma unroll
    for (int b = 0; b < BATCH; b++) g_opart[ks][b][n] = acc[b];
}

// ---------------- 6) sum O partials into d_out ----------------------------
__global__ void ocomb_k(float* __restrict__ out) {
    const int i = blockIdx.x * 256 + threadIdx.x;  // < 65536
    const float* p = &g_opart[0][0][0];
    float v = 0.f;
#pragma unroll
    for (int s = 0; s < KSPLIT; s++) v += p[(size_t)s * BATCH * HID + i];
    out[i] = v;
}

// ---------------- launch ---------------------------------------------------
extern "C" void kernel_launch(void* const* d_in, const int* in_sizes, int n_in,
                              void* d_out, int out_size) {
    const float* hidden  = (const float*)d_in[0];
    const float* k_cache = (const float*)d_in[1];
    const float* v_cache = (const float*)d_in[2];
    const float* w_qkv   = (const float*)d_in[3];
    const float* b_qkv   = (const float*)d_in[4];
    const float* w_o     = (const float*)d_in[5];
    const float* q_gamma = (const float*)d_in[6];
    const float* k_gamma = (const float*)d_in[7];
    float* out = (float*)d_out;

    qkv_gemm_k<<<dim3(QKVW / 128, KSPLIT), 128>>>(hidden, w_qkv);
    rmsnorm_k<<<dim3(QKVW / 128, BATCH), 128>>>(b_qkv, q_gamma, k_gamma);
    attn_k<<<dim3(NSPLIT, BATCH * NKV), 256>>>(k_cache, v_cache);
    combine_k<<<BATCH * NKV * GROUPS, 128>>>();
    o_gemm_k<<<dim3(HID / 128, KSPLIT), 128>>>(w_o);
    ocomb_k<<<(BATCH * HID) / 256, 256>>>(out);
}

// round 2
// speedup vs baseline: 1.0525x; 1.0525x over previous
#include <cuda_runtime.h>
#include <math_constants.h>

#define BATCH   32
#define LCACHE  8192
#define NKV     4
#define NH      16
#define HD      128
#define HID     2048
#define QKVW    3072          // 2048 q + 512 k + 512 v
#define GROUPS  4             // NH / NKV
#define NSPLIT  32
#define SPLIT_LEN 256         // LCACHE / NSPLIT
#define KSPLIT  16
#define AW      4             // warps per attn CTA
#define PDEPTH  4             // software pipeline depth (positions per warp in flight)

// scale * log2(e) : (1/sqrt(128)) * 1.4426950408889634
#define SCLOG2E (1.4426950408889634f * 0.08838834764831845f)

__device__ __forceinline__ float ex2(float x) {
    float y; asm("ex2.approx.ftz.f32 %0, %1;" : "=f"(y) : "f"(x)); return y;
}

// ---------------- scratch (device globals; no allocation allowed) ----------
__device__ float g_qkv_part[KSPLIT][BATCH][QKVW];      // 6.3 MB
__device__ float g_qn[BATCH][NH][HD];
__device__ float g_kn[BATCH][NKV][HD];
__device__ float g_vn[BATCH][NKV][HD];
__device__ float g_pacc[BATCH * NKV][NSPLIT][GROUPS][HD];  // 8.4 MB
__device__ float g_pm[BATCH * NKV][NSPLIT][GROUPS];
__device__ float g_pl[BATCH * NKV][NSPLIT][GROUPS];
__device__ float g_attn[BATCH][HID];
__device__ float g_opart[KSPLIT][BATCH][HID];          // 4.2 MB

// ---------------- 1) QKV GEMM: qkv_part[ks] = hidden_tile @ w_tile --------
__global__ void qkv_gemm_k(const float* __restrict__ hidden,
                           const float* __restrict__ w) {
    const int nblk = blockIdx.x;   // 0..23 (128 cols each)
    const int ks   = blockIdx.y;   // 0..15 (128 k each)
    const int tid  = threadIdx.x;  // 128

    __shared__ float hs[BATCH][128];
    for (int i = tid; i < BATCH * 128; i += 128) {
        int b = i >> 7, kk = i & 127;
        hs[b][kk] = hidden[b * HID + ks * 128 + kk];
    }
    __syncthreads();

    const int n = nblk * 128 + tid;
    float acc[BATCH];
#pragma unroll
    for (int b = 0; b < BATCH; b++) acc[b] = 0.f;

    const float* wp = w + (size_t)(ks * 128) * QKVW + n;
#pragma unroll 4
    for (int kk = 0; kk < 128; kk++) {
        float wv = __ldg(wp + (size_t)kk * QKVW);
#pragma unroll
        for (int b = 0; b < BATCH; b++) acc[b] += hs[b][kk] * wv;
    }
#pragma unroll
    for (int b = 0; b < BATCH; b++) g_qkv_part[ks][b][n] = acc[b];
}

// ---------------- 2) sum partials + bias + per-head RMSNorm ---------------
__global__ void rmsnorm_k(const float* __restrict__ b_qkv,
                          const float* __restrict__ q_gamma,
                          const float* __restrict__ k_gamma) {
    const int seg = blockIdx.x;   // 0..23 : 16 q heads, 4 k heads, 4 v heads
    const int b   = blockIdx.y;   // 0..31
    const int tid = threadIdx.x;  // 128 (= head_dim)
    const int col = seg * 128 + tid;

    float v = b_qkv[col];
#pragma unroll
    for (int s = 0; s < KSPLIT; s++) v += g_qkv_part[s][b][col];

    if (seg < 20) {
        float ss = v * v;
#pragma unroll
        for (int o = 16; o; o >>= 1) ss += __shfl_xor_sync(0xffffffffu, ss, o);
        __shared__ float wsum[4];
        if ((tid & 31) == 0) wsum[tid >> 5] = ss;
        __syncthreads();
        float tot = wsum[0] + wsum[1] + wsum[2] + wsum[3];
        float r = rsqrtf(tot * (1.f / 128.f) + 1e-6f);
        if (seg < 16) g_qn[b][seg][tid]      = v * r * q_gamma[tid];
        else          g_kn[b][seg - 16][tid] = v * r * k_gamma[tid];
    } else {
        g_vn[b][seg - 20][tid] = v;   // V: no norm
    }
}

// ---------------- 3) flash-decode split-K over the caches -----------------
// 128 threads (4 warps), warp handles positions split*256 + warp + 4*i,
// PDEPTH-deep software pipeline on the K/V loads.
__global__ void __launch_bounds__(128)
attn_k(const float* __restrict__ k_cache, const float* __restrict__ v_cache) {
    const int split = blockIdx.x;           // 0..31
    const int pair  = blockIdx.y;           // 0..127
    const int b     = pair >> 2;
    const int kv    = pair & 3;
    const int tid   = threadIdx.x;
    const int warp  = tid >> 5;
    const int lane  = tid & 31;

    __shared__ float qs[GROUPS][HD];
    __shared__ float s_acc[AW][GROUPS][HD];
    __shared__ float s_m[AW][GROUPS], s_l[AW][GROUPS], s_f[AW][GROUPS];
    __shared__ float s_gm[GROUPS], s_gl[GROUPS];

    for (int i = tid; i < GROUPS * HD; i += 128)
        qs[i >> 7][i & 127] = g_qn[b][kv * GROUPS + (i >> 7)][i & 127];
    __syncthreads();

    float qf[GROUPS][4];
#pragma unroll
    for (int h = 0; h < GROUPS; h++) {
        float4 q4 = *(const float4*)&qs[h][lane * 4];
        qf[h][0] = q4.x; qf[h][1] = q4.y; qf[h][2] = q4.z; qf[h][3] = q4.w;
    }

    float m[GROUPS], l[GROUPS], acc[GROUPS][4];
#pragma unroll
    for (int h = 0; h < GROUPS; h++) {
        m[h] = -CUDART_INF_F; l[h] = 0.f;
        acc[h][0] = acc[h][1] = acc[h][2] = acc[h][3] = 0.f;
    }

    const int end  = (split == NSPLIT - 1) ? (LCACHE + 1) : (split + 1) * SPLIT_LEN;
    const int pos0 = split * SPLIT_LEN + warp;

    const float* kbase = k_cache + ((size_t)b * LCACHE * NKV + kv) * HD;
    const float* vbase = v_cache + ((size_t)b * LCACHE * NKV + kv) * HD;

    float4 kb[PDEPTH], vb[PDEPTH];

    // prologue: fill the pipeline
#pragma unroll
    for (int j = 0; j < PDEPTH; j++) {
        int p = pos0 + j * AW;
        if (p < end) {
            const float4* kp = (p < LCACHE)
                ? (const float4*)(kbase + (size_t)p * NKV * HD)
                : (const float4*)&g_kn[b][kv][0];
            const float4* vp = (p < LCACHE)
                ? (const float4*)(vbase + (size_t)p * NKV * HD)
                : (const float4*)&g_vn[b][kv][0];
            kb[j] = __ldcs(kp + lane);
            vb[j] = __ldcs(vp + lane);
        }
    }

    for (int base = pos0; base < end; base += AW * PDEPTH) {
#pragma unroll
        for (int j = 0; j < PDEPTH; j++) {
            const int p = base + j * AW;
            if (p >= end) break;
            float4 k4 = kb[j], v4 = vb[j];

            // refill this slot with position p + AW*PDEPTH
            const int np = p + AW * PDEPTH;
            if (np < end) {
                const float4* kp = (np < LCACHE)
                    ? (const float4*)(kbase + (size_t)np * NKV * HD)
                    : (const float4*)&g_kn[b][kv][0];
                const float4* vp = (np < LCACHE)
                    ? (const float4*)(vbase + (size_t)np * NKV * HD)
                    : (const float4*)&g_vn[b][kv][0];
                kb[j] = __ldcs(kp + lane);
                vb[j] = __ldcs(vp + lane);
            }

            float s[GROUPS];
#pragma unroll
            for (int h = 0; h < GROUPS; h++)
                s[h] = qf[h][0] * k4.x + qf[h][1] * k4.y +
                       qf[h][2] * k4.z + qf[h][3] * k4.w;
#pragma unroll
            for (int o = 16; o; o >>= 1) {
#pragma unroll
                for (int h = 0; h < GROUPS; h++)
                    s[h] += __shfl_xor_sync(0xffffffffu, s[h], o);
            }

#pragma unroll
            for (int h = 0; h < GROUPS; h++) {
                float sv = s[h] * SCLOG2E;
                if (sv > m[h]) {
                    float alpha = ex2(m[h] - sv);   // 0 on first hit (m = -inf)
                    m[h] = sv;
                    l[h] = l[h] * alpha + 1.f;
                    acc[h][0] = acc[h][0] * alpha + v4.x;
                    acc[h][1] = acc[h][1] * alpha + v4.y;
                    acc[h][2] = acc[h][2] * alpha + v4.z;
                    acc[h][3] = acc[h][3] * alpha + v4.w;
                } else {
                    float pw = ex2(sv - m[h]);
                    l[h] += pw;
                    acc[h][0] += pw * v4.x;
                    acc[h][1] += pw * v4.y;
                    acc[h][2] += pw * v4.z;
                    acc[h][3] += pw * v4.w;
                }
            }
        }
    }

    // per-warp partials -> smem
#pragma unroll
    for (int h = 0; h < GROUPS; h++) {
        s_m[warp][h] = m[h];
        s_l[warp][h] = l[h];
        s_acc[warp][h][lane * 4 + 0] = acc[h][0];
        s_acc[warp][h][lane * 4 + 1] = acc[h][1];
        s_acc[warp][h][lane * 4 + 2] = acc[h][2];
        s_acc[warp][h][lane * 4 + 3] = acc[h][3];
    }
    __syncthreads();

    if (tid < GROUPS) {
        const int h = tid;
        float gm = -CUDART_INF_F;
#pragma unroll
        for (int w = 0; w < AW; w++) gm = fmaxf(gm, s_m[w][h]);
        float gl = 0.f;
#pragma unroll
        for (int w = 0; w < AW; w++) {
            float f = ex2(s_m[w][h] - gm);
            s_f[w][h] = f;
            gl += s_l[w][h] * f;
        }
        s_gm[h] = gm; s_gl[h] = gl;
    }
    __syncthreads();

    for (int i = tid; i < GROUPS * HD; i += 128) {
        const int h = i >> 7, d = i & 127;
        float num = 0.f;
#pragma unroll
        for (int w = 0; w < AW; w++) num += s_acc[w][h][d] * s_f[w][h];
        g_pacc[pair][split][h][d] = num;
        if (d == 0) { g_pm[pair][split][h] = s_gm[h]; g_pl[pair][split][h] = s_gl[h]; }
    }
}

// ---------------- 4) combine split partials -> attn_out -------------------
__global__ void combine_k() {
    const int idx  = blockIdx.x;     // 0..511
    const int pair = idx >> 2;
    const int g    = idx & 3;
    const int tid  = threadIdx.x;    // 128

    __shared__ float fs[NSPLIT];
    __shared__ float s_gl;
    if (tid < 32) {
        float pm = (tid < NSPLIT) ? g_pm[pair][tid][g] : -CUDART_INF_F;
        float pl = (tid < NSPLIT) ? g_pl[pair][tid][g] : 0.f;
        float gm = pm;
#pragma unroll
        for (int o = 16; o; o >>= 1) gm = fmaxf(gm, __shfl_xor_sync(0xffffffffu, gm, o));
        float f = ex2(pm - gm);
        float gl = pl * f;
#pragma unroll
        for (int o = 16; o; o >>= 1) gl += __shfl_xor_sync(0xffffffffu, gl, o);
        if (tid < NSPLIT) fs[tid] = f;
        if (tid == 0) s_gl = gl;
    }
    __syncthreads();

    float num = 0.f;
#pragma unroll
    for (int s = 0; s < NSPLIT; s++) num += g_pacc[pair][s][g][tid] * fs[s];

    const int b = pair >> 2, kv = pair & 3;
    g_attn[b][(kv * GROUPS + g) * HD + tid] = num / s_gl;
}

// ---------------- 5) O projection (k-split partials) ----------------------
__global__ void o_gemm_k(const float* __restrict__ w) {
    const int nblk = blockIdx.x;   // 0..15
    const int ks   = blockIdx.y;   // 0..15
    const int tid  = threadIdx.x;  // 128

    __shared__ float as_[BATCH][128];
    for (int i = tid; i < BATCH * 128; i += 128) {
        int b = i >> 7, kk = i & 127;
        as_[b][kk] = g_attn[b][ks * 128 + kk];
    }
    __syncthreads();

    const int n = nblk * 128 + tid;
    float acc[BATCH];
#pragma unroll
    for (int b = 0; b < BATCH; b++) acc[b] = 0.f;

    const float* wp = w + (size_t)(ks * 128) * HID + n;
#pragma unroll 4
    for (int kk = 0; kk < 128; kk++) {
        float wv = __ldg(wp + (size_t)kk * HID);
#pragma unroll
        for (int b = 0; b < BATCH; b++) acc[b] += as_[b][kk] * wv;
    }
#pragma unroll
    for (int b = 0; b < BATCH; b++) g_opart[ks][b][n] = acc[b];
}

// ---------------- 6) sum O partials into d_out ----------------------------
__global__ void ocomb_k(float* __restrict__ out) {
    const int i = blockIdx.x * 256 + threadIdx.x;  // < 65536
    const float* p = &g_opart[0][0][0];
    float v = 0.f;
#pragma unroll
    for (int s = 0; s < KSPLIT; s++) v += p[(size_t)s * BATCH * HID + i];
    out[i] = v;
}

// ---------------- launch ---------------------------------------------------
extern "C" void kernel_launch(void* const* d_in, const int* in_sizes, int n_in,
                              void* d_out, int out_size) {
    const float* hidden  = (const float*)d_in[0];
    const float* k_cache = (const float*)d_in[1];
    const float* v_cache = (const float*)d_in[2];
    const float* w_qkv   = (const float*)d_in[3];
    const float* b_qkv   = (const float*)d_in[4];
    const float* w_o     = (const float*)d_in[5];
    const float* q_gamma = (const float*)d_in[6];
    const float* k_gamma = (const float*)d_in[7];
    float* out = (float*)d_out;

    qkv_gemm_k<<<dim3(QKVW / 128, KSPLIT), 128>>>(hidden, w_qkv);
    rmsnorm_k<<<dim3(QKVW / 128, BATCH), 128>>>(b_qkv, q_gamma, k_gamma);
    attn_k<<<dim3(NSPLIT, BATCH * NKV), 128>>>(k_cache, v_cache);
    combine_k<<<BATCH * NKV * GROUPS, 128>>>();
    o_gemm_k<<<dim3(HID / 128, KSPLIT), 128>>>(w_o);
    ocomb_k<<<(BATCH * HID) / 256, 256>>>(out);
}

// round 3
// speedup vs baseline: 1.5868x; 1.5076x over previous
#include <cuda_runtime.h>
#include <math_constants.h>

#define BATCH   32
#define LCACHE  8192
#define NKV     4
#define NH      16
#define HD      128
#define HID     2048
#define QKVW    3072          // 2048 q + 512 k + 512 v
#define GROUPS  4             // NH / NKV
#define NSPLIT  32
#define SPLIT_LEN 256         // LCACHE / NSPLIT
#define KSPLIT  16
#define AW      4             // warps per attn CTA
#define WLEN    64            // positions per warp (SPLIT_LEN / AW)
#define PD      2             // pipeline depth in 2-position groups

// scale * log2(e) : (1/sqrt(128)) * 1.4426950408889634
#define SCLOG2E (1.4426950408889634f * 0.08838834764831845f)
#define FULLM   0xffffffffu

__device__ __forceinline__ float ex2(float x) {
    float y; asm("ex2.approx.ftz.f32 %0, %1;" : "=f"(y) : "f"(x)); return y;
}

// ---------------- scratch (device globals) ---------------------------------
__device__ float g_qkv_part[KSPLIT][BATCH][QKVW];
__device__ float g_qn[BATCH][NH][HD];
__device__ float g_kn[BATCH][NKV][HD];
__device__ float g_vn[BATCH][NKV][HD];
__device__ float g_pacc[BATCH * NKV][NSPLIT][GROUPS][HD];
__device__ float g_pm[BATCH * NKV][NSPLIT][GROUPS];
__device__ float g_pl[BATCH * NKV][NSPLIT][GROUPS];
__device__ float g_attn[BATCH][HID];
__device__ float g_opart[KSPLIT][BATCH][HID];

// ---------------- 1) QKV GEMM ----------------------------------------------
__global__ void qkv_gemm_k(const float* __restrict__ hidden,
                           const float* __restrict__ w) {
    const int nblk = blockIdx.x;
    const int ks   = blockIdx.y;
    const int tid  = threadIdx.x;

    __shared__ float hs[BATCH][128];
    for (int i = tid; i < BATCH * 128; i += 128) {
        int b = i >> 7, kk = i & 127;
        hs[b][kk] = hidden[b * HID + ks * 128 + kk];
    }
    __syncthreads();

    const int n = nblk * 128 + tid;
    float acc[BATCH];
#pragma unroll
    for (int b = 0; b < BATCH; b++) acc[b] = 0.f;

    const float* wp = w + (size_t)(ks * 128) * QKVW + n;
#pragma unroll 2
    for (int kk4 = 0; kk4 < 32; kk4++) {
        float w0 = __ldg(wp + (size_t)(kk4 * 4 + 0) * QKVW);
        float w1 = __ldg(wp + (size_t)(kk4 * 4 + 1) * QKVW);
        float w2 = __ldg(wp + (size_t)(kk4 * 4 + 2) * QKVW);
        float w3 = __ldg(wp + (size_t)(kk4 * 4 + 3) * QKVW);
#pragma unroll
        for (int b = 0; b < BATCH; b++) {
            float4 h4 = *(const float4*)&hs[b][kk4 * 4];
            acc[b] = fmaf(h4.x, w0, fmaf(h4.y, w1, fmaf(h4.z, w2, fmaf(h4.w, w3, acc[b]))));
        }
    }
#pragma unroll
    for (int b = 0; b < BATCH; b++) g_qkv_part[ks][b][n] = acc[b];
}

// ---------------- 2) sum partials + bias + per-head RMSNorm ----------------
__global__ void rmsnorm_k(const float* __restrict__ b_qkv,
                          const float* __restrict__ q_gamma,
                          const float* __restrict__ k_gamma) {
    const int seg = blockIdx.x;
    const int b   = blockIdx.y;
    const int tid = threadIdx.x;
    const int col = seg * 128 + tid;

    float v = b_qkv[col];
#pragma unroll
    for (int s = 0; s < KSPLIT; s++) v += g_qkv_part[s][b][col];

    if (seg < 20) {
        float ss = v * v;
#pragma unroll
        for (int o = 16; o; o >>= 1) ss += __shfl_xor_sync(FULLM, ss, o);
        __shared__ float wsum[4];
        if ((tid & 31) == 0) wsum[tid >> 5] = ss;
        __syncthreads();
        float tot = wsum[0] + wsum[1] + wsum[2] + wsum[3];
        float r = rsqrtf(tot * (1.f / 128.f) + 1e-6f);
        if (seg < 16) g_qn[b][seg][tid]      = v * r * q_gamma[tid];
        else          g_kn[b][seg - 16][tid] = v * r * k_gamma[tid];
    } else {
        g_vn[b][seg - 20][tid] = v;
    }
}

// ---------------- 3) flash-decode, packed butterfly reduction --------------
__global__ void __launch_bounds__(128)
attn_k(const float* __restrict__ k_cache, const float* __restrict__ v_cache) {
    const int split = blockIdx.x;
    const int pair  = blockIdx.y;
    const int b     = pair >> 2;
    const int kv    = pair & 3;
    const int tid   = threadIdx.x;
    const int warp  = tid >> 5;
    const int lane  = tid & 31;

    __shared__ float qs[GROUPS][HD];
    __shared__ float s_acc[AW][GROUPS][HD];
    __shared__ float s_m[AW][GROUPS], s_l[AW][GROUPS], s_f[AW][GROUPS];
    __shared__ float s_gm[GROUPS], s_gl[GROUPS];

    // q scaled by scale*log2e up-front
    for (int i = tid; i < GROUPS * HD; i += 128)
        qs[i >> 7][i & 127] = g_qn[b][kv * GROUPS + (i >> 7)][i & 127] * SCLOG2E;
    __syncthreads();

    float qf[GROUPS][4];
#pragma unroll
    for (int h = 0; h < GROUPS; h++) {
        float4 q4 = *(const float4*)&qs[h][lane * 4];
        qf[h][0] = q4.x; qf[h][1] = q4.y; qf[h][2] = q4.z; qf[h][3] = q4.w;
    }

    float m[GROUPS], l[GROUPS], acc[GROUPS][4];
#pragma unroll
    for (int h = 0; h < GROUPS; h++) {
        m[h] = -CUDART_INF_F; l[h] = 0.f;
        acc[h][0] = acc[h][1] = acc[h][2] = acc[h][3] = 0.f;
    }
    float m_own = -CUDART_INF_F;
    const int h_own = (lane >> 2) & 3;   // idx&3 of the value this lane ends with

    const int rs = split * SPLIT_LEN + warp * WLEN;
    int re = rs + WLEN;
    if (split == NSPLIT - 1 && warp == AW - 1) re += 1;  // new token at pos LCACHE

    const float* kbase = k_cache + ((size_t)b * LCACHE * NKV + kv) * HD;
    const float* vbase = v_cache + ((size_t)b * LCACHE * NKV + kv) * HD;

#define FETCHK(p) __ldcs(((p) < LCACHE ? (const float4*)(kbase + (size_t)(p) * NKV * HD) \
                                       : (const float4*)&g_kn[b][kv][0]) + lane)
#define FETCHV(p) __ldcs(((p) < LCACHE ? (const float4*)(vbase + (size_t)(p) * NKV * HD) \
                                       : (const float4*)&g_vn[b][kv][0]) + lane)

    float4 kb0[PD], kb1[PD], vb0[PD], vb1[PD];
#pragma unroll
    for (int j = 0; j < PD; j++) {        // WLEN >= 2*PD so all valid
        int p0 = rs + 2 * j, p1 = p0 + 1;
        kb0[j] = FETCHK(p0); vb0[j] = FETCHV(p0);
        kb1[j] = FETCHK(p1); vb1[j] = FETCHV(p1);
    }

    const bool hi16 = (lane & 16) != 0;
    const bool hi8  = (lane & 8) != 0;
    const bool hi4  = (lane & 4) != 0;

    for (int base = rs; base < re; base += 2 * PD) {
#pragma unroll
        for (int j = 0; j < PD; j++) {
            const int p0 = base + 2 * j;
            if (p0 >= re) break;
            const int p1 = p0 + 1;
            const bool tail = (p1 >= re);

            float4 k0 = kb0[j], k1 = kb1[j], v0 = vb0[j], v1 = vb1[j];

            const int n0 = p0 + 2 * PD;
            if (n0 < re) {
                int n1c = (n0 + 1 < re) ? n0 + 1 : re - 1;
                kb0[j] = FETCHK(n0);  vb0[j] = FETCHV(n0);
                kb1[j] = FETCHK(n1c); vb1[j] = FETCHV(n1c);
            }

            // 8 partial dots: idx = 4*p + h
            float a[8];
#pragma unroll
            for (int h = 0; h < GROUPS; h++) {
                a[h]     = qf[h][0] * k0.x + qf[h][1] * k0.y + qf[h][2] * k0.z + qf[h][3] * k0.w;
                a[4 + h] = qf[h][0] * k1.x + qf[h][1] * k1.y + qf[h][2] * k1.z + qf[h][3] * k1.w;
            }

            // pack-exchange reduction: 7 SHFL total
            float b4[4];
#pragma unroll
            for (int t = 0; t < 4; t++) {
                float send = hi16 ? a[t] : a[t + 4];
                float rcv  = __shfl_xor_sync(FULLM, send, 16);
                b4[t] = (hi16 ? a[t + 4] : a[t]) + rcv;
            }
            float c2[2];
#pragma unroll
            for (int t = 0; t < 2; t++) {
                float send = hi8 ? b4[t] : b4[t + 2];
                float rcv  = __shfl_xor_sync(FULLM, send, 8);
                c2[t] = (hi8 ? b4[t + 2] : b4[t]) + rcv;
            }
            {
                float send = hi4 ? c2[0] : c2[1];
                float rcv  = __shfl_xor_sync(FULLM, send, 4);
                c2[0] = (hi4 ? c2[1] : c2[0]) + rcv;
            }
            float d1 = c2[0];
            d1 += __shfl_xor_sync(FULLM, d1, 2);
            d1 += __shfl_xor_sync(FULLM, d1, 1);
            // lane L holds total for idx = 4*((L>>4)&1) + 2*((L>>3)&1) + ((L>>2)&1)
            // i.e. value idx i lives in lane 4*i;  idx = 4*p + h

            float pw  = ex2(d1 - m_own);
            bool  upd = d1 > m_own;

            if (__any_sync(FULLM, upd) | tail) {
                // slow path: full online-softmax update with rescale
#pragma unroll
                for (int h = 0; h < GROUPS; h++) {
                    float s0 = __shfl_sync(FULLM, d1, 4 * h);
                    float s1 = __shfl_sync(FULLM, d1, 16 + 4 * h);
                    if (tail) s1 = -CUDART_INF_F;
                    float mx = fmaxf(m[h], fmaxf(s0, s1));
                    float alpha = ex2(m[h] - mx);
                    float p0w = ex2(s0 - mx);
                    float p1w = ex2(s1 - mx);
                    m[h] = mx;
                    l[h] = fmaf(l[h], alpha, p0w + p1w);
                    acc[h][0] = fmaf(acc[h][0], alpha, fmaf(p0w, v0.x, p1w * v1.x));
                    acc[h][1] = fmaf(acc[h][1], alpha, fmaf(p0w, v0.y, p1w * v1.y));
                    acc[h][2] = fmaf(acc[h][2], alpha, fmaf(p0w, v0.z, p1w * v1.z));
                    acc[h][3] = fmaf(acc[h][3], alpha, fmaf(p0w, v0.w, p1w * v1.w));
                }
                m_own = (h_own == 0) ? m[0] : (h_own == 1) ? m[1] : (h_own == 2) ? m[2] : m[3];
            } else {
                // fast path: no max update anywhere; pw already valid
#pragma unroll
                for (int h = 0; h < GROUPS; h++) {
                    float p0w = __shfl_sync(FULLM, pw, 4 * h);
                    float p1w = __shfl_sync(FULLM, pw, 16 + 4 * h);
                    l[h] += p0w + p1w;
                    acc[h][0] = fmaf(p0w, v0.x, fmaf(p1w, v1.x, acc[h][0]));
                    acc[h][1] = fmaf(p0w, v0.y, fmaf(p1w, v1.y, acc[h][1]));
                    acc[h][2] = fmaf(p0w, v0.z, fmaf(p1w, v1.z, acc[h][2]));
                    acc[h][3] = fmaf(p0w, v0.w, fmaf(p1w, v1.w, acc[h][3]));
                }
            }
        }
    }

    // per-warp partials -> smem
#pragma unroll
    for (int h = 0; h < GROUPS; h++) {
        s_m[warp][h] = m[h];
        s_l[warp][h] = l[h];
        s_acc[warp][h][lane * 4 + 0] = acc[h][0];
        s_acc[warp][h][lane * 4 + 1] = acc[h][1];
        s_acc[warp][h][lane * 4 + 2] = acc[h][2];
        s_acc[warp][h][lane * 4 + 3] = acc[h][3];
    }
    __syncthreads();

    if (tid < GROUPS) {
        const int h = tid;
        float gm = -CUDART_INF_F;
#pragma unroll
        for (int w = 0; w < AW; w++) gm = fmaxf(gm, s_m[w][h]);
        float gl = 0.f;
#pragma unroll
        for (int w = 0; w < AW; w++) {
            float f = ex2(s_m[w][h] - gm);
            s_f[w][h] = f;
            gl += s_l[w][h] * f;
        }
        s_gm[h] = gm; s_gl[h] = gl;
    }
    __syncthreads();

    for (int i = tid; i < GROUPS * HD; i += 128) {
        const int h = i >> 7, d = i & 127;
        float num = 0.f;
#pragma unroll
        for (int w = 0; w < AW; w++) num += s_acc[w][h][d] * s_f[w][h];
        g_pacc[pair][split][h][d] = num;
        if (d == 0) { g_pm[pair][split][h] = s_gm[h]; g_pl[pair][split][h] = s_gl[h]; }
    }
}

// ---------------- 4) combine split partials -> attn_out --------------------
__global__ void combine_k() {
    const int idx  = blockIdx.x;
    const int pair = idx >> 2;
    const int g    = idx & 3;
    const int tid  = threadIdx.x;

    __shared__ float fs[NSPLIT];
    __shared__ float s_gl;
    if (tid < 32) {
        float pm = (tid < NSPLIT) ? g_pm[pair][tid][g] : -CUDART_INF_F;
        float pl = (tid < NSPLIT) ? g_pl[pair][tid][g] : 0.f;
        float gm = pm;
#pragma unroll
        for (int o = 16; o; o >>= 1) gm = fmaxf(gm, __shfl_xor_sync(FULLM, gm, o));
        float f = ex2(pm - gm);
        float gl = pl * f;
#pragma unroll
        for (int o = 16; o; o >>= 1) gl += __shfl_xor_sync(FULLM, gl, o);
        if (tid < NSPLIT) fs[tid] = f;
        if (tid == 0) s_gl = gl;
    }
    __syncthreads();

    float num = 0.f;
#pragma unroll
    for (int s = 0; s < NSPLIT; s++) num += g_pacc[pair][s][g][tid] * fs[s];

    const int b = pair >> 2, kv = pair & 3;
    g_attn[b][(kv * GROUPS + g) * HD + tid] = num / s_gl;
}

// ---------------- 5) O projection ------------------------------------------
__global__ void o_gemm_k(const float* __restrict__ w) {
    const int nblk = blockIdx.x;
    const int ks   = blockIdx.y;
    const int tid  = threadIdx.x;

    __shared__ float as_[BATCH][128];
    for (int i = tid; i < BATCH * 128; i += 128) {
        int b = i >> 7, kk = i & 127;
        as_[b][kk] = g_attn[b][ks * 128 + kk];
    }
    __syncthreads();

    const int n = nblk * 128 + tid;
    float acc[BATCH];
#pragma unroll
    for (int b = 0; b < BATCH; b++) acc[b] = 0.f;

    const float* wp = w + (size_t)(ks * 128) * HID + n;
#pragma unroll 2
    for (int kk4 = 0; kk4 < 32; kk4++) {
        float w0 = __ldg(wp + (size_t)(kk4 * 4 + 0) * HID);
        float w1 = __ldg(wp + (size_t)(kk4 * 4 + 1) * HID);
        float w2 = __ldg(wp + (size_t)(kk4 * 4 + 2) * HID);
        float w3 = __ldg(wp + (size_t)(kk4 * 4 + 3) * HID);
#pragma unroll
        for (int b = 0; b < BATCH; b++) {
            float4 h4 = *(const float4*)&as_[b][kk4 * 4];
            acc[b] = fmaf(h4.x, w0, fmaf(h4.y, w1, fmaf(h4.z, w2, fmaf(h4.w, w3, acc[b]))));
        }
    }
#pragma unroll
    for (int b = 0; b < BATCH; b++) g_opart[ks][b][n] = acc[b];
}

// ---------------- 6) sum O partials into d_out -----------------------------
__global__ void ocomb_k(float* __restrict__ out) {
    const int i = blockIdx.x * 256 + threadIdx.x;
    const float* p = &g_opart[0][0][0];
    float v = 0.f;
#pragma unroll
    for (int s = 0; s < KSPLIT; s++) v += p[(size_t)s * BATCH * HID + i];
    out[i] = v;
}

// ---------------- launch ----------------------------------------------------
extern "C" void kernel_launch(void* const* d_in, const int* in_sizes, int n_in,
                              void* d_out, int out_size) {
    const float* hidden  = (const float*)d_in[0];
    const float* k_cache = (const float*)d_in[1];
    const float* v_cache = (const float*)d_in[2];
    const float* w_qkv   = (const float*)d_in[3];
    const float* b_qkv   = (const float*)d_in[4];
    const float* w_o     = (const float*)d_in[5];
    const float* q_gamma = (const float*)d_in[6];
    const float* k_gamma = (const float*)d_in[7];
    float* out = (float*)d_out;

    qkv_gemm_k<<<dim3(QKVW / 128, KSPLIT), 128>>>(hidden, w_qkv);
    rmsnorm_k<<<dim3(QKVW / 128, BATCH), 128>>>(b_qkv, q_gamma, k_gamma);
    attn_k<<<dim3(NSPLIT, BATCH * NKV), 128>>>(k_cache, v_cache);
    combine_k<<<BATCH * NKV * GROUPS, 128>>>();
    o_gemm_k<<<dim3(HID / 128, KSPLIT), 128>>>(w_o);
    ocomb_k<<<(BATCH * HID) / 256, 256>>>(out);
}

// round 4
// speedup vs baseline: 1.6037x; 1.0107x over previous
#include <cuda_runtime.h>
#include <math_constants.h>

#define BATCH   32
#define LCACHE  8192
#define NKV     4
#define NH      16
#define HD      128
#define HID     2048
#define QKVW    3072          // 2048 q + 512 k + 512 v
#define GROUPS  4             // NH / NKV
#define NSPLIT  32
#define SPLIT_LEN 256         // LCACHE / NSPLIT
#define KSPLIT  16
#define AW      4             // warps per attn CTA
#define WLEN    64            // positions per warp (SPLIT_LEN / AW)
#define PD      2             // pipeline depth in 2-position groups

// scale * log2(e) : (1/sqrt(128)) * 1.4426950408889634
#define SCLOG2E (1.4426950408889634f * 0.08838834764831845f)
#define FULLM   0xffffffffu

__device__ __forceinline__ float ex2(float x) {
    float y; asm("ex2.approx.ftz.f32 %0, %1;" : "=f"(y) : "f"(x)); return y;
}

// ---------------- scratch (device globals) ---------------------------------
__device__ float g_qkv_part[KSPLIT][BATCH][QKVW];
__device__ float g_qn[BATCH][NH][HD];
__device__ float g_kn[BATCH][NKV][HD];
__device__ float g_vn[BATCH][NKV][HD];
__device__ float g_pacc[BATCH * NKV][NSPLIT][GROUPS][HD];
__device__ float g_pm[BATCH * NKV][NSPLIT][GROUPS];
__device__ float g_pl[BATCH * NKV][NSPLIT][GROUPS];
__device__ float g_attn[BATCH][HID];
__device__ float g_opart[KSPLIT][BATCH][HID];

// ---------------- 1) QKV GEMM ----------------------------------------------
__global__ void qkv_gemm_k(const float* __restrict__ hidden,
                           const float* __restrict__ w) {
    const int nblk = blockIdx.x;
    const int ks   = blockIdx.y;
    const int tid  = threadIdx.x;

    __shared__ float hs[BATCH][128];
    for (int i = tid; i < BATCH * 128; i += 128) {
        int b = i >> 7, kk = i & 127;
        hs[b][kk] = hidden[b * HID + ks * 128 + kk];
    }
    __syncthreads();

    const int n = nblk * 128 + tid;
    float acc[BATCH];
#pragma unroll
    for (int b = 0; b < BATCH; b++) acc[b] = 0.f;

    const float* wp = w + (size_t)(ks * 128) * QKVW + n;
#pragma unroll 2
    for (int kk4 = 0; kk4 < 32; kk4++) {
        float w0 = __ldg(wp + (size_t)(kk4 * 4 + 0) * QKVW);
        float w1 = __ldg(wp + (size_t)(kk4 * 4 + 1) * QKVW);
        float w2 = __ldg(wp + (size_t)(kk4 * 4 + 2) * QKVW);
        float w3 = __ldg(wp + (size_t)(kk4 * 4 + 3) * QKVW);
#pragma unroll
        for (int b = 0; b < BATCH; b++) {
            float4 h4 = *(const float4*)&hs[b][kk4 * 4];
            acc[b] = fmaf(h4.x, w0, fmaf(h4.y, w1, fmaf(h4.z, w2, fmaf(h4.w, w3, acc[b]))));
        }
    }
#pragma unroll
    for (int b = 0; b < BATCH; b++) g_qkv_part[ks][b][n] = acc[b];
}

// ---------------- 2) sum partials + bias + per-head RMSNorm ----------------
__global__ void rmsnorm_k(const float* __restrict__ b_qkv,
                          const float* __restrict__ q_gamma,
                          const float* __restrict__ k_gamma) {
    const int seg = blockIdx.x;
    const int b   = blockIdx.y;
    const int tid = threadIdx.x;
    const int col = seg * 128 + tid;

    float v = b_qkv[col];
#pragma unroll
    for (int s = 0; s < KSPLIT; s++) v += g_qkv_part[s][b][col];

    if (seg < 20) {
        float ss = v * v;
#pragma unroll
        for (int o = 16; o; o >>= 1) ss += __shfl_xor_sync(FULLM, ss, o);
        __shared__ float wsum[4];
        if ((tid & 31) == 0) wsum[tid >> 5] = ss;
        __syncthreads();
        float tot = wsum[0] + wsum[1] + wsum[2] + wsum[3];
        float r = rsqrtf(tot * (1.f / 128.f) + 1e-6f);
        if (seg < 16) g_qn[b][seg][tid]      = v * r * q_gamma[tid];
        else          g_kn[b][seg - 16][tid] = v * r * k_gamma[tid];
    } else {
        g_vn[b][seg - 20][tid] = v;
    }
}

// ---------------- 3) flash-decode, packed butterfly reduction --------------
__global__ void __launch_bounds__(128)
attn_k(const float* __restrict__ k_cache, const float* __restrict__ v_cache) {
    const int split = blockIdx.x;
    const int pair  = blockIdx.y;
    const int b     = pair >> 2;
    const int kv    = pair & 3;
    const int tid   = threadIdx.x;
    const int warp  = tid >> 5;
    const int lane  = tid & 31;

    __shared__ float qs[GROUPS][HD];
    __shared__ float s_acc[AW][GROUPS][HD];
    __shared__ float s_m[AW][GROUPS], s_l[AW][GROUPS], s_f[AW][GROUPS];
    __shared__ float s_gm[GROUPS], s_gl[GROUPS];

    // q scaled by scale*log2e up-front
    for (int i = tid; i < GROUPS * HD; i += 128)
        qs[i >> 7][i & 127] = g_qn[b][kv * GROUPS + (i >> 7)][i & 127] * SCLOG2E;
    __syncthreads();

    float qf[GROUPS][4];
#pragma unroll
    for (int h = 0; h < GROUPS; h++) {
        float4 q4 = *(const float4*)&qs[h][lane * 4];
        qf[h][0] = q4.x; qf[h][1] = q4.y; qf[h][2] = q4.z; qf[h][3] = q4.w;
    }

    float m[GROUPS], l[GROUPS], acc[GROUPS][4];
#pragma unroll
    for (int h = 0; h < GROUPS; h++) {
        m[h] = -CUDART_INF_F; l[h] = 0.f;
        acc[h][0] = acc[h][1] = acc[h][2] = acc[h][3] = 0.f;
    }
    float m_own = -CUDART_INF_F;
    const int h_own = (lane >> 2) & 3;   // idx&3 of the value this lane ends with

    const int rs = split * SPLIT_LEN + warp * WLEN;
    int re = rs + WLEN;
    if (split == NSPLIT - 1 && warp == AW - 1) re += 1;  // new token at pos LCACHE

    const float* kbase = k_cache + ((size_t)b * LCACHE * NKV + kv) * HD;
    const float* vbase = v_cache + ((size_t)b * LCACHE * NKV + kv) * HD;

#define FETCHK(p) __ldcs(((p) < LCACHE ? (const float4*)(kbase + (size_t)(p) * NKV * HD) \
                                       : (const float4*)&g_kn[b][kv][0]) + lane)
#define FETCHV(p) __ldcs(((p) < LCACHE ? (const float4*)(vbase + (size_t)(p) * NKV * HD) \
                                       : (const float4*)&g_vn[b][kv][0]) + lane)

    float4 kb0[PD], kb1[PD], vb0[PD], vb1[PD];
#pragma unroll
    for (int j = 0; j < PD; j++) {        // WLEN >= 2*PD so all valid
        int p0 = rs + 2 * j, p1 = p0 + 1;
        kb0[j] = FETCHK(p0); vb0[j] = FETCHV(p0);
        kb1[j] = FETCHK(p1); vb1[j] = FETCHV(p1);
    }

    const bool hi16 = (lane & 16) != 0;
    const bool hi8  = (lane & 8) != 0;
    const bool hi4  = (lane & 4) != 0;

    for (int base = rs; base < re; base += 2 * PD) {
#pragma unroll
        for (int j = 0; j < PD; j++) {
            const int p0 = base + 2 * j;
            if (p0 >= re) break;
            const int p1 = p0 + 1;
            const bool tail = (p1 >= re);

            float4 k0 = kb0[j], k1 = kb1[j], v0 = vb0[j], v1 = vb1[j];

            const int n0 = p0 + 2 * PD;
            if (n0 < re) {
                int n1c = (n0 + 1 < re) ? n0 + 1 : re - 1;
                kb0[j] = FETCHK(n0);  vb0[j] = FETCHV(n0);
                kb1[j] = FETCHK(n1c); vb1[j] = FETCHV(n1c);
            }

            // 8 partial dots: idx = 4*p + h
            float a[8];
#pragma unroll
            for (int h = 0; h < GROUPS; h++) {
                a[h]     = qf[h][0] * k0.x + qf[h][1] * k0.y + qf[h][2] * k0.z + qf[h][3] * k0.w;
                a[4 + h] = qf[h][0] * k1.x + qf[h][1] * k1.y + qf[h][2] * k1.z + qf[h][3] * k1.w;
            }

            // pack-exchange reduction: 7 SHFL total
            float b4[4];
#pragma unroll
            for (int t = 0; t < 4; t++) {
                float send = hi16 ? a[t] : a[t + 4];
                float rcv  = __shfl_xor_sync(FULLM, send, 16);
                b4[t] = (hi16 ? a[t + 4] : a[t]) + rcv;
            }
            float c2[2];
#pragma unroll
            for (int t = 0; t < 2; t++) {
                float send = hi8 ? b4[t] : b4[t + 2];
                float rcv  = __shfl_xor_sync(FULLM, send, 8);
                c2[t] = (hi8 ? b4[t + 2] : b4[t]) + rcv;
            }
            {
                float send = hi4 ? c2[0] : c2[1];
                float rcv  = __shfl_xor_sync(FULLM, send, 4);
                c2[0] = (hi4 ? c2[1] : c2[0]) + rcv;
            }
            float d1 = c2[0];
            d1 += __shfl_xor_sync(FULLM, d1, 2);
            d1 += __shfl_xor_sync(FULLM, d1, 1);
            // lane L holds total for idx = 4*((L>>4)&1) + 2*((L>>3)&1) + ((L>>2)&1)
            // i.e. value idx i lives in lane 4*i;  idx = 4*p + h

            float pw  = ex2(d1 - m_own);
            bool  upd = d1 > m_own;

            if (__any_sync(FULLM, upd) | tail) {
                // slow path: full online-softmax update with rescale
#pragma unroll
                for (int h = 0; h < GROUPS; h++) {
                    float s0 = __shfl_sync(FULLM, d1, 4 * h);
                    float s1 = __shfl_sync(FULLM, d1, 16 + 4 * h);
                    if (tail) s1 = -CUDART_INF_F;
                    float mx = fmaxf(m[h], fmaxf(s0, s1));
                    float alpha = ex2(m[h] - mx);
                    float p0w = ex2(s0 - mx);
                    float p1w = ex2(s1 - mx);
                    m[h] = mx;
                    l[h] = fmaf(l[h], alpha, p0w + p1w);
                    acc[h][0] = fmaf(acc[h][0], alpha, fmaf(p0w, v0.x, p1w * v1.x));
                    acc[h][1] = fmaf(acc[h][1], alpha, fmaf(p0w, v0.y, p1w * v1.y));
                    acc[h][2] = fmaf(acc[h][2], alpha, fmaf(p0w, v0.z, p1w * v1.z));
                    acc[h][3] = fmaf(acc[h][3], alpha, fmaf(p0w, v0.w, p1w * v1.w));
                }
                m_own = (h_own == 0) ? m[0] : (h_own == 1) ? m[1] : (h_own == 2) ? m[2] : m[3];
            } else {
                // fast path: no max update anywhere; pw already valid
#pragma unroll
                for (int h = 0; h < GROUPS; h++) {
                    float p0w = __shfl_sync(FULLM, pw, 4 * h);
                    float p1w = __shfl_sync(FULLM, pw, 16 + 4 * h);
                    l[h] += p0w + p1w;
                    acc[h][0] = fmaf(p0w, v0.x, fmaf(p1w, v1.x, acc[h][0]));
                    acc[h][1] = fmaf(p0w, v0.y, fmaf(p1w, v1.y, acc[h][1]));
                    acc[h][2] = fmaf(p0w, v0.z, fmaf(p1w, v1.z, acc[h][2]));
                    acc[h][3] = fmaf(p0w, v0.w, fmaf(p1w, v1.w, acc[h][3]));
                }
            }
        }
    }

    // per-warp partials -> smem
#pragma unroll
    for (int h = 0; h < GROUPS; h++) {
        s_m[warp][h] = m[h];
        s_l[warp][h] = l[h];
        s_acc[warp][h][lane * 4 + 0] = acc[h][0];
        s_acc[warp][h][lane * 4 + 1] = acc[h][1];
        s_acc[warp][h][lane * 4 + 2] = acc[h][2];
        s_acc[warp][h][lane * 4 + 3] = acc[h][3];
    }
    __syncthreads();

    if (tid < GROUPS) {
        const int h = tid;
        float gm = -CUDART_INF_F;
#pragma unroll
        for (int w = 0; w < AW; w++) gm = fmaxf(gm, s_m[w][h]);
        float gl = 0.f;
#pragma unroll
        for (int w = 0; w < AW; w++) {
            float f = ex2(s_m[w][h] - gm);
            s_f[w][h] = f;
            gl += s_l[w][h] * f;
        }
        s_gm[h] = gm; s_gl[h] = gl;
    }
    __syncthreads();

    for (int i = tid; i < GROUPS * HD; i += 128) {
        const int h = i >> 7, d = i & 127;
        float num = 0.f;
#pragma unroll
        for (int w = 0; w < AW; w++) num += s_acc[w][h][d] * s_f[w][h];
        g_pacc[pair][split][h][d] = num;
        if (d == 0) { g_pm[pair][split][h] = s_gm[h]; g_pl[pair][split][h] = s_gl[h]; }
    }
}

// ---------------- 4) combine split partials -> attn_out --------------------
__global__ void combine_k() {
    const int idx  = blockIdx.x;
    const int pair = idx >> 2;
    const int g    = idx & 3;
    const int tid  = threadIdx.x;

    __shared__ float fs[NSPLIT];
    __shared__ float s_gl;
    if (tid < 32) {
        float pm = (tid < NSPLIT) ? g_pm[pair][tid][g] : -CUDART_INF_F;
        float pl = (tid < NSPLIT) ? g_pl[pair][tid][g] : 0.f;
        float gm = pm;
#pragma unroll
        for (int o = 16; o; o >>= 1) gm = fmaxf(gm, __shfl_xor_sync(FULLM, gm, o));
        float f = ex2(pm - gm);
        float gl = pl * f;
#pragma unroll
        for (int o = 16; o; o >>= 1) gl += __shfl_xor_sync(FULLM, gl, o);
        if (tid < NSPLIT) fs[tid] = f;
        if (tid == 0) s_gl = gl;
    }
    __syncthreads();

    float num = 0.f;
#pragma unroll
    for (int s = 0; s < NSPLIT; s++) num += g_pacc[pair][s][g][tid] * fs[s];

    const int b = pair >> 2, kv = pair & 3;
    g_attn[b][(kv * GROUPS + g) * HD + tid] = num / s_gl;
}

// ---------------- 5) O projection ------------------------------------------
__global__ void o_gemm_k(const float* __restrict__ w) {
    const int nblk = blockIdx.x;
    const int ks   = blockIdx.y;
    const int tid  = threadIdx.x;

    __shared__ float as_[BATCH][128];
    for (int i = tid; i < BATCH * 128; i += 128) {
        int b = i >> 7, kk = i & 127;
        as_[b][kk] = g_attn[b][ks * 128 + kk];
    }
    __syncthreads();

    const int n = nblk * 128 + tid;
    float acc[BATCH];
#pragma unroll
    for (int b = 0; b < BATCH; b++) acc[b] = 0.f;

    const float* wp = w + (size_t)(ks * 128) * HID + n;
#pragma unroll 2
    for (int kk4 = 0; kk4 < 32; kk4++) {
        float w0 = __ldg(wp + (size_t)(kk4 * 4 + 0) * HID);
        float w1 = __ldg(wp + (size_t)(kk4 * 4 + 1) * HID);
        float w2 = __ldg(wp + (size_t)(kk4 * 4 + 2) * HID);
        float w3 = __ldg(wp + (size_t)(kk4 * 4 + 3) * HID);
#pragma unroll
        for (int b = 0; b < BATCH; b++) {
            float4 h4 = *(const float4*)&as_[b][kk4 * 4];
            acc[b] = fmaf(h4.x, w0, fmaf(h4.y, w1, fmaf(h4.z, w2, fmaf(h4.w, w3, acc[b]))));
        }
    }
#pragma unroll
    for (int b = 0; b < BATCH; b++) g_opart[ks][b][n] = acc[b];
}

// ---------------- 6) sum O partials into d_out -----------------------------
__global__ void ocomb_k(float* __restrict__ out) {
    const int i = blockIdx.x * 256 + threadIdx.x;
    const float* p = &g_opart[0][0][0];
    float v = 0.f;
#pragma unroll
    for (int s = 0; s < KSPLIT; s++) v += p[(size_t)s * BATCH * HID + i];
    out[i] = v;
}

// ---------------- launch ----------------------------------------------------
extern "C" void kernel_launch(void* const* d_in, const int* in_sizes, int n_in,
                              void* d_out, int out_size) {
    const float* hidden  = (const float*)d_in[0];
    const float* k_cache = (const float*)d_in[1];
    const float* v_cache = (const float*)d_in[2];
    const float* w_qkv   = (const float*)d_in[3];
    const float* b_qkv   = (const float*)d_in[4];
    const float* w_o     = (const float*)d_in[5];
    const float* q_gamma = (const float*)d_in[6];
    const float* k_gamma = (const float*)d_in[7];
    float* out = (float*)d_out;

    qkv_gemm_k<<<dim3(QKVW / 128, KSPLIT), 128>>>(hidden, w_qkv);
    rmsnorm_k<<<dim3(QKVW / 128, BATCH), 128>>>(b_qkv, q_gamma, k_gamma);
    attn_k<<<dim3(NSPLIT, BATCH * NKV), 128>>>(k_cache, v_cache);
    combine_k<<<BATCH * NKV * GROUPS, 128>>>();
    o_gemm_k<<<dim3(HID / 128, KSPLIT), 128>>>(w_o);
    ocomb_k<<<(BATCH * HID) / 256, 256>>>(out);
}